// round 8
// baseline (speedup 1.0000x reference)
#include <cuda_runtime.h>
#include <cstdint>

#define MAX_NODES 100000
#define D 64

// ---------------- scratch (device globals: no allocation allowed) ----------
__device__ float g_pre_dst[(size_t)MAX_NODES * D];  // x@W1a + (u@W1d + b1)[batch]
__device__ float g_pre_src[(size_t)MAX_NODES * D];  // x@W1b
__device__ float g_agg[(size_t)MAX_NODES * D];      // scatter-sum target
__device__ float g_ugb[16 * D];                     // u@W1d + b1 per graph
__device__ float g_uc2[16 * D];                     // u@W2c + b2 per graph

// ---------------- packed f32x2 helpers (Blackwell FFMA2) -------------------
__device__ __forceinline__ unsigned long long fma2(unsigned long long a,
                                                   unsigned long long b,
                                                   unsigned long long c) {
    unsigned long long d;
    asm("fma.rn.f32x2 %0, %1, %2, %3;" : "=l"(d) : "l"(a), "l"(b), "l"(c));
    return d;
}
__device__ __forceinline__ unsigned long long pack2(float x, float y) {
    unsigned long long r;
    asm("mov.b64 %0, {%1, %2};" : "=l"(r) : "f"(x), "f"(y));
    return r;
}
__device__ __forceinline__ float2 unpack2(unsigned long long v) {
    float2 r;
    asm("mov.b64 {%0, %1}, %2;" : "=f"(r.x), "=f"(r.y) : "l"(v));
    return r;
}

// ---------------- noop: aligns edge_fused with ncu capture slot 3 -----------
__global__ void noop_k() {}

// ---------------- per-graph tables ------------------------------------------
__global__ void init_k(const float* __restrict__ u,
                       const float* __restrict__ W1, const float* __restrict__ b1,
                       const float* __restrict__ W2, const float* __restrict__ b2) {
    int j = threadIdx.x & 63;
    int g = threadIdx.x >> 6;   // 1024 threads = 16 graphs x 64 cols
    float s1 = b1[j], s2 = b2[j];
#pragma unroll
    for (int k = 0; k < 32; k++) {
        float uv = u[g * 32 + k];
        s1 += uv * W1[(160 + k) * 64 + j];
        s2 += uv * W2[(128 + k) * 64 + j];
    }
    g_ugb[g * 64 + j] = s1;
    g_uc2[g * 64 + j] = s2;
}

// ---------------- fused node pre-GEMM (also zeroes g_agg) -------------------
__global__ __launch_bounds__(256) void node_pre(
    const float* __restrict__ x, const float* __restrict__ W1,
    const float* __restrict__ ugb, const int* __restrict__ batch, int N) {
    __shared__ float sXT[64][68];
    __shared__ float sW[64][64];
    const int tid = threadIdx.x;
    const int tn = tid & 15;
    const int tj = tid >> 4;
    const int node0 = blockIdx.x * 64;

    // zero this block's slice of g_agg
    {
        float4* ap = reinterpret_cast<float4*>(g_agg + (size_t)node0 * 64);
        int limit = (N - node0) * 16;
        if (limit > 1024) limit = 1024;
        for (int i = tid; i < limit; i += 256)
            ap[i] = make_float4(0.f, 0.f, 0.f, 0.f);
    }

    for (int i = tid; i < 4096; i += 256) {
        int r = i >> 6, c = i & 63;
        int n = node0 + r;
        sXT[c][r] = (n < N) ? x[(size_t)n * 64 + c] : 0.f;
    }

    unsigned long long acc[2][4][2];
#pragma unroll
    for (int a = 0; a < 2; a++)
#pragma unroll
        for (int i = 0; i < 4; i++) { acc[a][i][0] = 0ull; acc[a][i][1] = 0ull; }

    for (int a = 0; a < 2; a++) {
        __syncthreads();
        for (int i = tid; i < 4096; i += 256) {
            int k = i >> 6, j = i & 63;
            sW[k][j] = W1[(size_t)(a * 64 + k) * 64 + j];
        }
        __syncthreads();
#pragma unroll 8
        for (int k = 0; k < 64; k++) {
            float4 xv = *reinterpret_cast<const float4*>(&sXT[k][tn * 4]);
            ulonglong2 wv = *reinterpret_cast<const ulonglong2*>(&sW[k][tj * 4]);
            unsigned long long xd;
            xd = pack2(xv.x, xv.x);
            acc[a][0][0] = fma2(xd, wv.x, acc[a][0][0]); acc[a][0][1] = fma2(xd, wv.y, acc[a][0][1]);
            xd = pack2(xv.y, xv.y);
            acc[a][1][0] = fma2(xd, wv.x, acc[a][1][0]); acc[a][1][1] = fma2(xd, wv.y, acc[a][1][1]);
            xd = pack2(xv.z, xv.z);
            acc[a][2][0] = fma2(xd, wv.x, acc[a][2][0]); acc[a][2][1] = fma2(xd, wv.y, acc[a][2][1]);
            xd = pack2(xv.w, xv.w);
            acc[a][3][0] = fma2(xd, wv.x, acc[a][3][0]); acc[a][3][1] = fma2(xd, wv.y, acc[a][3][1]);
        }
    }

#pragma unroll
    for (int nn = 0; nn < 4; nn++) {
        int n = node0 + tn * 4 + nn;
        if (n < N) {
            float2 p0 = unpack2(acc[0][nn][0]);
            float2 p1 = unpack2(acc[0][nn][1]);
            int g = __ldg(batch + n);
            float4 tv = *reinterpret_cast<const float4*>(ugb + g * 64 + tj * 4);
            float4 o = make_float4(p0.x + tv.x, p0.y + tv.y, p1.x + tv.z, p1.y + tv.w);
            *reinterpret_cast<float4*>(g_pre_dst + (size_t)n * 64 + tj * 4) = o;
            p0 = unpack2(acc[1][nn][0]);
            p1 = unpack2(acc[1][nn][1]);
            float4 o2 = make_float4(p0.x, p0.y, p1.x, p1.y);
            *reinterpret_cast<float4*>(g_pre_src + (size_t)n * 64 + tj * 4) = o2;
        }
    }
}

// ---------------- fused edge GEMM + scatter epilogue -------------------------
// CTA = 64 edges x 64 cols. ea tile transposed to smem, W1c in smem (no
// per-lane weight registers -> high occupancy). Thread = 4 edges x 4 cols.
// Epilogue: gather pre_dst/pre_src float4s, add, ReLU, red.global.add.v4.
__global__ __launch_bounds__(256) void edge_fused(
    const int* __restrict__ ei, const float* __restrict__ ea,
    const float* __restrict__ W1, int E) {
    __shared__ float sET[32][68];   // [k][edge], padded
    __shared__ float sW[32][64];    // W1c [k][col]
    __shared__ int sSrc[64], sDst[64];
    const int tid = threadIdx.x;
    const int e0 = blockIdx.x * 64;

    // ea tile (transposed): consecutive tid -> consecutive k of one edge (coalesced)
    for (int i = tid; i < 2048; i += 256) {
        int edge = i >> 5, k = i & 31;
        int e = e0 + edge;
        sET[k][edge] = (e < E) ? __ldg(ea + (size_t)e * 32 + k) : 0.f;
    }
    // W1c block (rows 128..159 of W1)
    for (int i = tid; i < 2048; i += 256) {
        int k = i >> 6, j = i & 63;
        sW[k][j] = __ldg(W1 + (size_t)(128 + k) * 64 + j);
    }
    if (tid < 64) {
        int e = e0 + tid;
        sSrc[tid] = (e < E) ? __ldg(ei + e) : 0;
    } else if (tid < 128) {
        int t = tid - 64;
        int e = e0 + t;
        sDst[t] = (e < E) ? __ldg(ei + E + e) : 0;
    }
    __syncthreads();

    const int tn = tid & 15;   // edge group (4 edges)
    const int tj = tid >> 4;   // col group (4 cols)

    unsigned long long acc[4][2];
#pragma unroll
    for (int i = 0; i < 4; i++) { acc[i][0] = 0ull; acc[i][1] = 0ull; }

#pragma unroll 8
    for (int k = 0; k < 32; k++) {
        float4 xv = *reinterpret_cast<const float4*>(&sET[k][tn * 4]);
        ulonglong2 wv = *reinterpret_cast<const ulonglong2*>(&sW[k][tj * 4]);
        unsigned long long xd;
        xd = pack2(xv.x, xv.x);
        acc[0][0] = fma2(xd, wv.x, acc[0][0]); acc[0][1] = fma2(xd, wv.y, acc[0][1]);
        xd = pack2(xv.y, xv.y);
        acc[1][0] = fma2(xd, wv.x, acc[1][0]); acc[1][1] = fma2(xd, wv.y, acc[1][1]);
        xd = pack2(xv.z, xv.z);
        acc[2][0] = fma2(xd, wv.x, acc[2][0]); acc[2][1] = fma2(xd, wv.y, acc[2][1]);
        xd = pack2(xv.w, xv.w);
        acc[3][0] = fma2(xd, wv.x, acc[3][0]); acc[3][1] = fma2(xd, wv.y, acc[3][1]);
    }

    // epilogue: batch independent gathers first (MLP=8), then atomics
    float4 pd[4], ps[4];
    int dst[4];
    bool live[4];
#pragma unroll
    for (int nn = 0; nn < 4; nn++) {
        int ee = tn * 4 + nn;
        live[nn] = (e0 + ee) < E;
        dst[nn] = sDst[ee];
        int src = sSrc[ee];
        if (live[nn]) {
            pd[nn] = __ldg(reinterpret_cast<const float4*>(g_pre_dst + (size_t)dst[nn] * 64) + tj);
            ps[nn] = __ldg(reinterpret_cast<const float4*>(g_pre_src + (size_t)src * 64) + tj);
        }
    }
#pragma unroll
    for (int nn = 0; nn < 4; nn++) {
        if (live[nn]) {
            float2 p0 = unpack2(acc[nn][0]);
            float2 p1 = unpack2(acc[nn][1]);
            float v0 = fmaxf(p0.x + pd[nn].x + ps[nn].x, 0.f);
            float v1 = fmaxf(p0.y + pd[nn].y + ps[nn].y, 0.f);
            float v2 = fmaxf(p1.x + pd[nn].z + ps[nn].z, 0.f);
            float v3 = fmaxf(p1.y + pd[nn].w + ps[nn].w, 0.f);
            float* ap = g_agg + (size_t)dst[nn] * 64 + tj * 4;
            asm volatile("red.global.add.v4.f32 [%0], {%1, %2, %3, %4};"
                         :: "l"(ap), "f"(v0), "f"(v1), "f"(v2), "f"(v3)
                         : "memory");
        }
    }
}

// ---------------- final node GEMM --------------------------------------------
__global__ __launch_bounds__(256) void dense_final(
    const float* __restrict__ x, const float* __restrict__ W2,
    const float* __restrict__ uc2, const int* __restrict__ batch,
    float* __restrict__ out, int N) {
    __shared__ float sXT[64][68];
    __shared__ float sW[64][64];
    const int tid = threadIdx.x;
    const int tn = tid & 15;
    const int tj = tid >> 4;
    const int node0 = blockIdx.x * 64;

    unsigned long long acc[4][2];
#pragma unroll
    for (int i = 0; i < 4; i++) { acc[i][0] = 0ull; acc[i][1] = 0ull; }

    for (int a = 0; a < 2; a++) {
        const float* __restrict__ A = (a == 0) ? x : g_agg;
        for (int i = tid; i < 4096; i += 256) {
            int r = i >> 6, c = i & 63;
            int n = node0 + r;
            sXT[c][r] = (n < N) ? A[(size_t)n * 64 + c] : 0.f;
        }
        for (int i = tid; i < 4096; i += 256) {
            int k = i >> 6, j = i & 63;
            sW[k][j] = W2[(size_t)(a * 64 + k) * 64 + j];
        }
        __syncthreads();
#pragma unroll 8
        for (int k = 0; k < 64; k++) {
            float4 xv = *reinterpret_cast<const float4*>(&sXT[k][tn * 4]);
            ulonglong2 wv = *reinterpret_cast<const ulonglong2*>(&sW[k][tj * 4]);
            unsigned long long xd;
            xd = pack2(xv.x, xv.x);
            acc[0][0] = fma2(xd, wv.x, acc[0][0]); acc[0][1] = fma2(xd, wv.y, acc[0][1]);
            xd = pack2(xv.y, xv.y);
            acc[1][0] = fma2(xd, wv.x, acc[1][0]); acc[1][1] = fma2(xd, wv.y, acc[1][1]);
            xd = pack2(xv.z, xv.z);
            acc[2][0] = fma2(xd, wv.x, acc[2][0]); acc[2][1] = fma2(xd, wv.y, acc[2][1]);
            xd = pack2(xv.w, xv.w);
            acc[3][0] = fma2(xd, wv.x, acc[3][0]); acc[3][1] = fma2(xd, wv.y, acc[3][1]);
        }
        __syncthreads();
    }

#pragma unroll
    for (int nn = 0; nn < 4; nn++) {
        int n = node0 + tn * 4 + nn;
        if (n < N) {
            float2 p0 = unpack2(acc[nn][0]);
            float2 p1 = unpack2(acc[nn][1]);
            int g = __ldg(batch + n);
            float4 tv = *reinterpret_cast<const float4*>(uc2 + g * 64 + tj * 4);
            float4 o = make_float4(fmaxf(p0.x + tv.x, 0.f), fmaxf(p0.y + tv.y, 0.f),
                                   fmaxf(p1.x + tv.z, 0.f), fmaxf(p1.y + tv.w, 0.f));
            *reinterpret_cast<float4*>(out + (size_t)n * 64 + tj * 4) = o;
        }
    }
}

// ---------------- launch ------------------------------------------------------
extern "C" void kernel_launch(void* const* d_in, const int* in_sizes, int n_in,
                              void* d_out, int out_size) {
    const float* x     = (const float*)d_in[0];
    const int*   ei    = (const int*)d_in[1];
    const float* ea    = (const float*)d_in[2];
    const float* u     = (const float*)d_in[3];
    const int*   batch = (const int*)d_in[4];
    const float* W1    = (const float*)d_in[5];
    const float* b1    = (const float*)d_in[6];
    const float* W2    = (const float*)d_in[7];
    const float* b2    = (const float*)d_in[8];
    float* out = (float*)d_out;

    const int N = in_sizes[0] / 64;   // 100000
    const int E = in_sizes[2] / 32;   // 1000000

    float *ugb, *uc2;
    cudaGetSymbolAddress((void**)&ugb, g_ugb);
    cudaGetSymbolAddress((void**)&uc2, g_uc2);

    // 0: per-graph tables
    init_k<<<1, 1024>>>(u, W1, b1, W2, b2);
    // 1: fused pre_dst + pre_src (+ zero g_agg)
    node_pre<<<(N + 63) / 64, 256>>>(x, W1, ugb, batch, N);
    // 2: noop (ncu capture slot is empirically index 3)
    noop_k<<<1, 32>>>();
    // 3: fused edge GEMM + scatter  <-- ncu capture
    edge_fused<<<(E + 63) / 64, 256>>>(ei, ea, W1, E);
    // 4: final node MLP
    dense_final<<<(N + 63) / 64, 256>>>(x, W2, uc2, batch, out, N);
}

// round 10
// speedup vs baseline: 1.0878x; 1.0878x over previous
#include <cuda_runtime.h>
#include <cstdint>

#define MAX_NODES 100000
#define D 64

// ---------------- scratch (device globals: no allocation allowed) ----------
__device__ float g_pre_dst[(size_t)MAX_NODES * D];  // x@W1a + (u@W1d + b1)[batch]
__device__ float g_pre_src[(size_t)MAX_NODES * D];  // x@W1b
__device__ float g_agg[(size_t)MAX_NODES * D];      // scatter-sum target
__device__ float g_ugb[16 * D];                     // u@W1d + b1 per graph
__device__ float g_uc2[16 * D];                     // u@W2c + b2 per graph

// ---------------- packed f32x2 helpers (Blackwell FFMA2) -------------------
__device__ __forceinline__ unsigned long long fma2(unsigned long long a,
                                                   unsigned long long b,
                                                   unsigned long long c) {
    unsigned long long d;
    asm("fma.rn.f32x2 %0, %1, %2, %3;" : "=l"(d) : "l"(a), "l"(b), "l"(c));
    return d;
}
__device__ __forceinline__ unsigned long long pack2(float x, float y) {
    unsigned long long r;
    asm("mov.b64 %0, {%1, %2};" : "=l"(r) : "f"(x), "f"(y));
    return r;
}
__device__ __forceinline__ float2 unpack2(unsigned long long v) {
    float2 r;
    asm("mov.b64 {%0, %1}, %2;" : "=f"(r.x), "=f"(r.y) : "l"(v));
    return r;
}

// ---------------- noop: aligns edge_fused with ncu capture slot 3 -----------
__global__ void noop_k() {}

// ---------------- per-graph tables ------------------------------------------
__global__ void init_k(const float* __restrict__ u,
                       const float* __restrict__ W1, const float* __restrict__ b1,
                       const float* __restrict__ W2, const float* __restrict__ b2) {
    int j = threadIdx.x & 63;
    int g = threadIdx.x >> 6;   // 1024 threads = 16 graphs x 64 cols
    float s1 = b1[j], s2 = b2[j];
#pragma unroll
    for (int k = 0; k < 32; k++) {
        float uv = u[g * 32 + k];
        s1 += uv * W1[(160 + k) * 64 + j];
        s2 += uv * W2[(128 + k) * 64 + j];
    }
    g_ugb[g * 64 + j] = s1;
    g_uc2[g * 64 + j] = s2;
}

// ---------------- fused node pre-GEMM (also zeroes g_agg) -------------------
__global__ __launch_bounds__(256) void node_pre(
    const float* __restrict__ x, const float* __restrict__ W1,
    const float* __restrict__ ugb, const int* __restrict__ batch, int N) {
    __shared__ float sXT[64][68];
    __shared__ float sW[64][64];
    const int tid = threadIdx.x;
    const int tn = tid & 15;
    const int tj = tid >> 4;
    const int node0 = blockIdx.x * 64;

    // zero this block's slice of g_agg
    {
        float4* ap = reinterpret_cast<float4*>(g_agg + (size_t)node0 * 64);
        int limit = (N - node0) * 16;
        if (limit > 1024) limit = 1024;
        for (int i = tid; i < limit; i += 256)
            ap[i] = make_float4(0.f, 0.f, 0.f, 0.f);
    }

    for (int i = tid; i < 4096; i += 256) {
        int r = i >> 6, c = i & 63;
        int n = node0 + r;
        sXT[c][r] = (n < N) ? x[(size_t)n * 64 + c] : 0.f;
    }

    unsigned long long acc[2][4][2];
#pragma unroll
    for (int a = 0; a < 2; a++)
#pragma unroll
        for (int i = 0; i < 4; i++) { acc[a][i][0] = 0ull; acc[a][i][1] = 0ull; }

    for (int a = 0; a < 2; a++) {
        __syncthreads();
        for (int i = tid; i < 4096; i += 256) {
            int k = i >> 6, j = i & 63;
            sW[k][j] = W1[(size_t)(a * 64 + k) * 64 + j];
        }
        __syncthreads();
#pragma unroll 8
        for (int k = 0; k < 64; k++) {
            float4 xv = *reinterpret_cast<const float4*>(&sXT[k][tn * 4]);
            ulonglong2 wv = *reinterpret_cast<const ulonglong2*>(&sW[k][tj * 4]);
            unsigned long long xd;
            xd = pack2(xv.x, xv.x);
            acc[a][0][0] = fma2(xd, wv.x, acc[a][0][0]); acc[a][0][1] = fma2(xd, wv.y, acc[a][0][1]);
            xd = pack2(xv.y, xv.y);
            acc[a][1][0] = fma2(xd, wv.x, acc[a][1][0]); acc[a][1][1] = fma2(xd, wv.y, acc[a][1][1]);
            xd = pack2(xv.z, xv.z);
            acc[a][2][0] = fma2(xd, wv.x, acc[a][2][0]); acc[a][2][1] = fma2(xd, wv.y, acc[a][2][1]);
            xd = pack2(xv.w, xv.w);
            acc[a][3][0] = fma2(xd, wv.x, acc[a][3][0]); acc[a][3][1] = fma2(xd, wv.y, acc[a][3][1]);
        }
    }

#pragma unroll
    for (int nn = 0; nn < 4; nn++) {
        int n = node0 + tn * 4 + nn;
        if (n < N) {
            float2 p0 = unpack2(acc[0][nn][0]);
            float2 p1 = unpack2(acc[0][nn][1]);
            int g = __ldg(batch + n);
            float4 tv = *reinterpret_cast<const float4*>(ugb + g * 64 + tj * 4);
            float4 o = make_float4(p0.x + tv.x, p0.y + tv.y, p1.x + tv.z, p1.y + tv.w);
            *reinterpret_cast<float4*>(g_pre_dst + (size_t)n * 64 + tj * 4) = o;
            p0 = unpack2(acc[1][nn][0]);
            p1 = unpack2(acc[1][nn][1]);
            float4 o2 = make_float4(p0.x, p0.y, p1.x, p1.y);
            *reinterpret_cast<float4*>(g_pre_src + (size_t)n * 64 + tj * 4) = o2;
        }
    }
}

// ---------------- fused edge GEMM + scatter epilogue -------------------------
// CTA = 128 edges x 64 cols, 256 threads. Micro-tile = 4 edges x 8 cols
// (smem bytes/FMA = 1.5, FMA-pipe bound instead of crossbar bound).
// tn = tid>>3 (32 groups of 4 edges), tj = tid&7 (8 groups of 8 cols).
__global__ __launch_bounds__(256) void edge_fused(
    const int* __restrict__ ei, const float* __restrict__ ea,
    const float* __restrict__ W1, int E) {
    __shared__ float sET[32][132];  // [k][edge], 4-float pad
    __shared__ float sW[32][64];    // W1c [k][col]
    __shared__ int sSrc[128], sDst[128];
    const int tid = threadIdx.x;
    const int e0 = blockIdx.x * 128;

    // ea tile (transposed): 32 consecutive tid = 32 k of one edge (coalesced LDG)
    for (int i = tid; i < 4096; i += 256) {
        int edge = i >> 5, k = i & 31;
        int e = e0 + edge;
        sET[k][edge] = (e < E) ? __ldg(ea + (size_t)e * 32 + k) : 0.f;
    }
    // W1c block (rows 128..159 of W1)
    for (int i = tid; i < 2048; i += 256) {
        int k = i >> 6, j = i & 63;
        sW[k][j] = __ldg(W1 + (size_t)(128 + k) * 64 + j);
    }
    if (tid < 128) {
        int e = e0 + tid;
        sSrc[tid] = (e < E) ? __ldg(ei + e) : 0;
    } else {
        int t = tid - 128;
        int e = e0 + t;
        sDst[t] = (e < E) ? __ldg(ei + E + e) : 0;
    }
    __syncthreads();

    const int tn = tid >> 3;   // edge group (4 edges)
    const int tj = tid & 7;    // col group (8 cols)

    unsigned long long acc[4][4];   // [edge][col f32x2 pair]
#pragma unroll
    for (int i = 0; i < 4; i++)
#pragma unroll
        for (int c = 0; c < 4; c++) acc[i][c] = 0ull;

#pragma unroll 8
    for (int k = 0; k < 32; k++) {
        float4 xv = *reinterpret_cast<const float4*>(&sET[k][tn * 4]);
        ulonglong2 w0 = *reinterpret_cast<const ulonglong2*>(&sW[k][tj * 8]);
        ulonglong2 w1 = *reinterpret_cast<const ulonglong2*>(&sW[k][tj * 8 + 4]);
        unsigned long long xd;
        xd = pack2(xv.x, xv.x);
        acc[0][0] = fma2(xd, w0.x, acc[0][0]); acc[0][1] = fma2(xd, w0.y, acc[0][1]);
        acc[0][2] = fma2(xd, w1.x, acc[0][2]); acc[0][3] = fma2(xd, w1.y, acc[0][3]);
        xd = pack2(xv.y, xv.y);
        acc[1][0] = fma2(xd, w0.x, acc[1][0]); acc[1][1] = fma2(xd, w0.y, acc[1][1]);
        acc[1][2] = fma2(xd, w1.x, acc[1][2]); acc[1][3] = fma2(xd, w1.y, acc[1][3]);
        xd = pack2(xv.z, xv.z);
        acc[2][0] = fma2(xd, w0.x, acc[2][0]); acc[2][1] = fma2(xd, w0.y, acc[2][1]);
        acc[2][2] = fma2(xd, w1.x, acc[2][2]); acc[2][3] = fma2(xd, w1.y, acc[2][3]);
        xd = pack2(xv.w, xv.w);
        acc[3][0] = fma2(xd, w0.x, acc[3][0]); acc[3][1] = fma2(xd, w0.y, acc[3][1]);
        acc[3][2] = fma2(xd, w1.x, acc[3][2]); acc[3][3] = fma2(xd, w1.y, acc[3][3]);
    }

    // epilogue: per edge, 4 independent gathers (MLP=4), add, ReLU, 2x red.v4
#pragma unroll
    for (int nn = 0; nn < 4; nn++) {
        int ee = tn * 4 + nn;
        if (e0 + ee < E) {
            int d = sDst[ee];
            int s = sSrc[ee];
            const float4* pdp = reinterpret_cast<const float4*>(g_pre_dst + (size_t)d * 64);
            const float4* psp = reinterpret_cast<const float4*>(g_pre_src + (size_t)s * 64);
            float4 pd0 = __ldg(pdp + tj * 2);
            float4 pd1 = __ldg(pdp + tj * 2 + 1);
            float4 ps0 = __ldg(psp + tj * 2);
            float4 ps1 = __ldg(psp + tj * 2 + 1);
            float2 a0 = unpack2(acc[nn][0]);
            float2 a1 = unpack2(acc[nn][1]);
            float2 a2 = unpack2(acc[nn][2]);
            float2 a3 = unpack2(acc[nn][3]);
            float v0 = fmaxf(a0.x + pd0.x + ps0.x, 0.f);
            float v1 = fmaxf(a0.y + pd0.y + ps0.y, 0.f);
            float v2 = fmaxf(a1.x + pd0.z + ps0.z, 0.f);
            float v3 = fmaxf(a1.y + pd0.w + ps0.w, 0.f);
            float v4 = fmaxf(a2.x + pd1.x + ps1.x, 0.f);
            float v5 = fmaxf(a2.y + pd1.y + ps1.y, 0.f);
            float v6 = fmaxf(a3.x + pd1.z + ps1.z, 0.f);
            float v7 = fmaxf(a3.y + pd1.w + ps1.w, 0.f);
            float* ap = g_agg + (size_t)d * 64 + tj * 8;
            asm volatile("red.global.add.v4.f32 [%0], {%1, %2, %3, %4};"
                         :: "l"(ap), "f"(v0), "f"(v1), "f"(v2), "f"(v3) : "memory");
            asm volatile("red.global.add.v4.f32 [%0], {%1, %2, %3, %4};"
                         :: "l"(ap + 4), "f"(v4), "f"(v5), "f"(v6), "f"(v7) : "memory");
        }
    }
}

// ---------------- final node GEMM --------------------------------------------
__global__ __launch_bounds__(256) void dense_final(
    const float* __restrict__ x, const float* __restrict__ W2,
    const float* __restrict__ uc2, const int* __restrict__ batch,
    float* __restrict__ out, int N) {
    __shared__ float sXT[64][68];
    __shared__ float sW[64][64];
    const int tid = threadIdx.x;
    const int tn = tid & 15;
    const int tj = tid >> 4;
    const int node0 = blockIdx.x * 64;

    unsigned long long acc[4][2];
#pragma unroll
    for (int i = 0; i < 4; i++) { acc[i][0] = 0ull; acc[i][1] = 0ull; }

    for (int a = 0; a < 2; a++) {
        const float* __restrict__ A = (a == 0) ? x : g_agg;
        for (int i = tid; i < 4096; i += 256) {
            int r = i >> 6, c = i & 63;
            int n = node0 + r;
            sXT[c][r] = (n < N) ? A[(size_t)n * 64 + c] : 0.f;
        }
        for (int i = tid; i < 4096; i += 256) {
            int k = i >> 6, j = i & 63;
            sW[k][j] = W2[(size_t)(a * 64 + k) * 64 + j];
        }
        __syncthreads();
#pragma unroll 8
        for (int k = 0; k < 64; k++) {
            float4 xv = *reinterpret_cast<const float4*>(&sXT[k][tn * 4]);
            ulonglong2 wv = *reinterpret_cast<const ulonglong2*>(&sW[k][tj * 4]);
            unsigned long long xd;
            xd = pack2(xv.x, xv.x);
            acc[0][0] = fma2(xd, wv.x, acc[0][0]); acc[0][1] = fma2(xd, wv.y, acc[0][1]);
            xd = pack2(xv.y, xv.y);
            acc[1][0] = fma2(xd, wv.x, acc[1][0]); acc[1][1] = fma2(xd, wv.y, acc[1][1]);
            xd = pack2(xv.z, xv.z);
            acc[2][0] = fma2(xd, wv.x, acc[2][0]); acc[2][1] = fma2(xd, wv.y, acc[2][1]);
            xd = pack2(xv.w, xv.w);
            acc[3][0] = fma2(xd, wv.x, acc[3][0]); acc[3][1] = fma2(xd, wv.y, acc[3][1]);
        }
        __syncthreads();
    }

#pragma unroll
    for (int nn = 0; nn < 4; nn++) {
        int n = node0 + tn * 4 + nn;
        if (n < N) {
            float2 p0 = unpack2(acc[nn][0]);
            float2 p1 = unpack2(acc[nn][1]);
            int g = __ldg(batch + n);
            float4 tv = *reinterpret_cast<const float4*>(uc2 + g * 64 + tj * 4);
            float4 o = make_float4(fmaxf(p0.x + tv.x, 0.f), fmaxf(p0.y + tv.y, 0.f),
                                   fmaxf(p1.x + tv.z, 0.f), fmaxf(p1.y + tv.w, 0.f));
            *reinterpret_cast<float4*>(out + (size_t)n * 64 + tj * 4) = o;
        }
    }
}

// ---------------- launch ------------------------------------------------------
extern "C" void kernel_launch(void* const* d_in, const int* in_sizes, int n_in,
                              void* d_out, int out_size) {
    const float* x     = (const float*)d_in[0];
    const int*   ei    = (const int*)d_in[1];
    const float* ea    = (const float*)d_in[2];
    const float* u     = (const float*)d_in[3];
    const int*   batch = (const int*)d_in[4];
    const float* W1    = (const float*)d_in[5];
    const float* b1    = (const float*)d_in[6];
    const float* W2    = (const float*)d_in[7];
    const float* b2    = (const float*)d_in[8];
    float* out = (float*)d_out;

    const int N = in_sizes[0] / 64;   // 100000
    const int E = in_sizes[2] / 32;   // 1000000

    float *ugb, *uc2;
    cudaGetSymbolAddress((void**)&ugb, g_ugb);
    cudaGetSymbolAddress((void**)&uc2, g_uc2);

    // 0: per-graph tables
    init_k<<<1, 1024>>>(u, W1, b1, W2, b2);
    // 1: fused pre_dst + pre_src (+ zero g_agg)
    node_pre<<<(N + 63) / 64, 256>>>(x, W1, ugb, batch, N);
    // 2: noop (ncu capture slot is empirically index 3)
    noop_k<<<1, 32>>>();
    // 3: fused edge GEMM + scatter  <-- ncu capture
    edge_fused<<<(E + 127) / 128, 256>>>(ei, ea, W1, E);
    // 4: final node MLP
    dense_final<<<(N + 63) / 64, 256>>>(x, W2, uc2, batch, out, N);
}